// round 6
// baseline (speedup 1.0000x reference)
#include <cuda_runtime.h>

#define NWIN 64
#define HD   32
#define NH   6
#define ATT_SCALE 0.17677669529663687f   // 32^-0.5
#define LOG2E 1.4426950408889634f
#define WARPS_PER_CTA 6
#define NTHREADS (WARPS_PER_CTA * 32)

typedef unsigned long long u64;

__device__ float g_biasT[NH * NWIN * NWIN];  // [h][m][interleaved row], *log2e

static __device__ __forceinline__ u64 fma2(u64 a, u64 b, u64 c) {
    u64 d;
    asm("fma.rn.f32x2 %0, %1, %2, %3;" : "=l"(d) : "l"(a), "l"(b), "l"(c));
    return d;
}
static __device__ __forceinline__ u64 add2(u64 a, u64 b) {
    u64 d;
    asm("add.rn.f32x2 %0, %1, %2;" : "=l"(d) : "l"(a), "l"(b));
    return d;
}
static __device__ __forceinline__ u64 mul2(u64 a, u64 b) {
    u64 d;
    asm("mul.rn.f32x2 %0, %1, %2;" : "=l"(d) : "l"(a), "l"(b));
    return d;
}
static __device__ __forceinline__ u64 pack2(float x, float y) {
    u64 d;
    asm("mov.b64 %0, {%1, %2};" : "=l"(d) : "f"(x), "f"(y));
    return d;
}
static __device__ __forceinline__ float2 unpack2(u64 u) {
    float2 r;
    asm("mov.b64 {%0, %1}, %2;" : "=f"(r.x), "=f"(r.y) : "l"(u));
    return r;
}
static __device__ __forceinline__ float ex2f(float x) {
    float y;
    asm("ex2.approx.ftz.f32 %0, %1;" : "=f"(y) : "f"(x));
    return y;
}

// ---------------------------------------------------------------------------
// Kernel 1: relative-position bias MLP  [64,64,2] -> g_biasT[h][m][ir]
//   ir interleaves rows: ir = 2*(r&31) + (r>>5), value pre-scaled by log2(e)
// ---------------------------------------------------------------------------
__global__ void __launch_bounds__(256)
bias_kernel(const float* __restrict__ rel, const float* __restrict__ w1,
            const float* __restrict__ b1, const float* __restrict__ w2,
            const float* __restrict__ b2) {
    __shared__ float s_w1a[256];
    __shared__ float s_w1b[256];
    __shared__ float s_b1[256];
    __shared__ float s_w2[256 * NH];

    const int tid = threadIdx.x;
    s_w1a[tid] = w1[tid];
    s_w1b[tid] = w1[256 + tid];
    s_b1[tid]  = b1[tid];
#pragma unroll
    for (int i = tid; i < 256 * NH; i += 256) s_w2[i] = w2[i];
    __syncthreads();

    const int idx = blockIdx.x * 256 + tid;  // r*64 + m
    const float r0 = rel[idx * 2 + 0];
    const float r1 = rel[idx * 2 + 1];

    float acc[NH];
#pragma unroll
    for (int o = 0; o < NH; o++) acc[o] = 0.0f;

#pragma unroll 4
    for (int hh = 0; hh < 256; hh++) {
        float a = fmaf(r0, s_w1a[hh], fmaf(r1, s_w1b[hh], s_b1[hh]));
        a = fmaxf(a, 0.0f);
#pragma unroll
        for (int o = 0; o < NH; o++) acc[o] = fmaf(a, s_w2[hh * NH + o], acc[o]);
    }
    const int r = idx >> 6;
    const int m = idx & 63;
    const int ir = ((r & 31) << 1) | (r >> 5);
#pragma unroll
    for (int o = 0; o < NH; o++)
        g_biasT[o * 4096 + m * 64 + ir] = (acc[o] + b2[o]) * LOG2E;
}

// ---------------------------------------------------------------------------
// Kernel 2: one WARP = one (b,h) window. Lane owns query rows {lane, lane+32}.
//   q pre-scaled by SCALE*log2e; bias seeded into the dot accumulator, so the
//   per-m serial path is add2 -> fadd -> ex2.
// ---------------------------------------------------------------------------
__global__ void __launch_bounds__(NTHREADS, 2)
attn_kernel(const float* __restrict__ qkv, float* __restrict__ out) {
    extern __shared__ float smem[];
    float* sbias = smem;  // 4096 floats, shared by all warps (same h)

    const int tid  = threadIdx.x;
    const int lane = tid & 31;
    const int w    = tid >> 5;
    const int h    = blockIdx.x;
    const int b    = blockIdx.y * WARPS_PER_CTA + w;
    const bool active = (b < 2048);

    float* sk = smem + 4096 + w * 4096;  // 64 x 32
    float* sv = sk + 2048;               // 64 x 32

    // ---- stage bias tile (all threads participate) ----------------------
    {
        const float4* gb = (const float4*)(g_biasT + h * 4096);
#pragma unroll
        for (int i = tid; i < 1024; i += NTHREADS)
            ((float4*)sbias)[i] = gb[i];
    }

    // ---- stage k, v into per-warp smem + scaled q rows into registers ---
    ulonglong2 q0[8], q1[8];
    if (active) {
        const float* base = qkv + (size_t)b * (NWIN * 576) + h * HD;
        const int r4 = lane >> 3;  // 0..3
        const int f  = lane & 7;   // 0..7
#pragma unroll
        for (int i = 0; i < 16; i++) {
            const int n = i * 4 + r4;
            const float* g = base + n * 576 + f * 4;
            float4 kx = *(const float4*)(g + 192);
            float4 vx = *(const float4*)(g + 384);
            *(float4*)(sk + n * 32 + f * 4) = kx;
            *(float4*)(sv + n * 32 + f * 4) = vx;
        }
        const float* qr0 = base + lane * 576;
        const float* qr1 = base + (lane + 32) * 576;
        const u64 sc = pack2(ATT_SCALE * LOG2E, ATT_SCALE * LOG2E);
#pragma unroll
        for (int i = 0; i < 8; i++) {
            ulonglong2 a = *(const ulonglong2*)(qr0 + i * 4);
            ulonglong2 c = *(const ulonglong2*)(qr1 + i * 4);
            q0[i].x = mul2(a.x, sc); q0[i].y = mul2(a.y, sc);
            q1[i].x = mul2(c.x, sc); q1[i].y = mul2(c.y, sc);
        }
    }
    __syncthreads();
    if (!active) return;

    // ---- streaming attention over key index m ---------------------------
    u64 o0[16], o1[16];
#pragma unroll
    for (int j = 0; j < 16; j++) { o0[j] = 0ull; o1[j] = 0ull; }
    u64 sums = 0ull;  // (sum row0, sum row1)

    const float* bias_l = sbias + 2 * lane;

#pragma unroll 2
    for (int m = 0; m < NWIN; m++) {
        const ulonglong2* krow = (const ulonglong2*)(sk + m * 32);
        const ulonglong2* vrow = (const ulonglong2*)(sv + m * 32);

        // v rows issued first: consumed only after the dot+exp chain,
        // so their LDS latency is fully hidden by the dot math.
        ulonglong2 vx[8];
#pragma unroll
        for (int j = 0; j < 8; j++) vx[j] = vrow[j];

        float2 bf = unpack2(*(const u64*)(bias_l + m * 64));  // log2e-scaled

        // dot products (packed over d), bias seeded into chain a
        u64 d0a = pack2(bf.x, 0.0f), d0b = 0ull;
        u64 d1a = pack2(bf.y, 0.0f), d1b = 0ull;
#pragma unroll
        for (int j = 0; j < 8; j += 2) {
            ulonglong2 ka = krow[j];
            ulonglong2 kb = krow[j + 1];
            d0a = fma2(q0[j].x, ka.x, d0a);
            d0b = fma2(q0[j].y, ka.y, d0b);
            d1a = fma2(q1[j].x, ka.x, d1a);
            d1b = fma2(q1[j].y, ka.y, d1b);
            d0a = fma2(q0[j + 1].x, kb.x, d0a);
            d0b = fma2(q0[j + 1].y, kb.y, d0b);
            d1a = fma2(q1[j + 1].x, kb.x, d1a);
            d1b = fma2(q1[j + 1].y, kb.y, d1b);
        }
        float2 p0 = unpack2(add2(d0a, d0b));
        float2 p1 = unpack2(add2(d1a, d1b));
        float e0 = ex2f(p0.x + p0.y);
        float e1 = ex2f(p1.x + p1.y);
        sums = add2(sums, pack2(e0, e1));
        const u64 e0p = pack2(e0, e0);
        const u64 e1p = pack2(e1, e1);

#pragma unroll
        for (int j = 0; j < 8; j++) {
            o0[2 * j]     = fma2(e0p, vx[j].x, o0[2 * j]);
            o0[2 * j + 1] = fma2(e0p, vx[j].y, o0[2 * j + 1]);
            o1[2 * j]     = fma2(e1p, vx[j].x, o1[2 * j]);
            o1[2 * j + 1] = fma2(e1p, vx[j].y, o1[2 * j + 1]);
        }
    }

    // ---- epilogue: normalize + store ------------------------------------
    float2 s = unpack2(sums);
    const float inv0 = 1.0f / s.x;
    const float inv1 = 1.0f / s.y;

    float* orow0 = out + (size_t)b * (NWIN * 192) + lane * 192 + h * HD;
    float* orow1 = orow0 + 32 * 192;
#pragma unroll
    for (int j = 0; j < 8; j++) {
        float2 a0 = unpack2(o0[2 * j]);
        float2 a1 = unpack2(o0[2 * j + 1]);
        *(float4*)(orow0 + 4 * j) =
            make_float4(a0.x * inv0, a0.y * inv0, a1.x * inv0, a1.y * inv0);
        float2 c0 = unpack2(o1[2 * j]);
        float2 c1 = unpack2(o1[2 * j + 1]);
        *(float4*)(orow1 + 4 * j) =
            make_float4(c0.x * inv1, c0.y * inv1, c1.x * inv1, c1.y * inv1);
    }
}

// ---------------------------------------------------------------------------
extern "C" void kernel_launch(void* const* d_in, const int* in_sizes, int n_in,
                              void* d_out, int out_size) {
    const float* qkv = (const float*)d_in[0];
    const float* rel = (const float*)d_in[1];
    const float* w1  = (const float*)d_in[2];
    const float* b1  = (const float*)d_in[3];
    const float* w2  = (const float*)d_in[4];
    const float* b2  = (const float*)d_in[5];
    float* out = (float*)d_out;

    const int smem_bytes = (4096 + WARPS_PER_CTA * 4096) * sizeof(float);  // 112 KB
    cudaFuncSetAttribute(attn_kernel, cudaFuncAttributeMaxDynamicSharedMemorySize,
                         smem_bytes);

    bias_kernel<<<16, 256>>>(rel, w1, b1, w2, b2);
    const int gy = (2048 + WARPS_PER_CTA - 1) / WARPS_PER_CTA;  // 342
    attn_kernel<<<dim3(NH, gy), NTHREADS, smem_bytes>>>(qkv, out);
}

// round 7
// speedup vs baseline: 1.0413x; 1.0413x over previous
#include <cuda_runtime.h>

#define NWIN 64
#define HD   32
#define NH   6
#define ATT_SCALE 0.17677669529663687f   // 32^-0.5
#define LOG2E 1.4426950408889634f
#define WARPS_PER_CTA 5
#define NTHREADS (WARPS_PER_CTA * 32)

typedef unsigned long long u64;

__device__ float g_biasT[NH * NWIN * NWIN];  // [h][m][interleaved row], *log2e

static __device__ __forceinline__ u64 fma2(u64 a, u64 b, u64 c) {
    u64 d;
    asm("fma.rn.f32x2 %0, %1, %2, %3;" : "=l"(d) : "l"(a), "l"(b), "l"(c));
    return d;
}
static __device__ __forceinline__ u64 add2(u64 a, u64 b) {
    u64 d;
    asm("add.rn.f32x2 %0, %1, %2;" : "=l"(d) : "l"(a), "l"(b));
    return d;
}
static __device__ __forceinline__ u64 pack2(float x, float y) {
    u64 d;
    asm("mov.b64 %0, {%1, %2};" : "=l"(d) : "f"(x), "f"(y));
    return d;
}
static __device__ __forceinline__ float2 unpack2(u64 u) {
    float2 r;
    asm("mov.b64 {%0, %1}, %2;" : "=f"(r.x), "=f"(r.y) : "l"(u));
    return r;
}
static __device__ __forceinline__ float ex2f(float x) {
    float y;
    asm("ex2.approx.ftz.f32 %0, %1;" : "=f"(y) : "f"(x));
    return y;
}

// ---------------------------------------------------------------------------
// Kernel 1: relative-position bias MLP  [64,64,2] -> g_biasT[h][m][ir]
//   ir interleaves rows: ir = 2*(r&31) + (r>>5), value pre-scaled by log2(e)
// ---------------------------------------------------------------------------
__global__ void __launch_bounds__(256)
bias_kernel(const float* __restrict__ rel, const float* __restrict__ w1,
            const float* __restrict__ b1, const float* __restrict__ w2,
            const float* __restrict__ b2) {
    __shared__ float s_w1a[256];
    __shared__ float s_w1b[256];
    __shared__ float s_b1[256];
    __shared__ float s_w2[256 * NH];

    const int tid = threadIdx.x;
    s_w1a[tid] = w1[tid];
    s_w1b[tid] = w1[256 + tid];
    s_b1[tid]  = b1[tid];
#pragma unroll
    for (int i = tid; i < 256 * NH; i += 256) s_w2[i] = w2[i];
    __syncthreads();

    const int idx = blockIdx.x * 256 + tid;  // r*64 + m
    const float r0 = rel[idx * 2 + 0];
    const float r1 = rel[idx * 2 + 1];

    float acc[NH];
#pragma unroll
    for (int o = 0; o < NH; o++) acc[o] = 0.0f;

#pragma unroll 4
    for (int hh = 0; hh < 256; hh++) {
        float a = fmaf(r0, s_w1a[hh], fmaf(r1, s_w1b[hh], s_b1[hh]));
        a = fmaxf(a, 0.0f);
#pragma unroll
        for (int o = 0; o < NH; o++) acc[o] = fmaf(a, s_w2[hh * NH + o], acc[o]);
    }
    const int r = idx >> 6;
    const int m = idx & 63;
    const int ir = ((r & 31) << 1) | (r >> 5);
#pragma unroll
    for (int o = 0; o < NH; o++)
        g_biasT[o * 4096 + m * 64 + ir] = (acc[o] + b2[o]) * LOG2E;
}

// ---------------------------------------------------------------------------
// Kernel 2: one WARP = one (b,h) window. Lane owns query rows {lane, lane+32}.
//   Software-pipelined over m: PV(m-1) hides k(m) LDS latency; v(m) and e(m)
//   are produced at iter m and consumed at iter m+1 (all latencies off-path).
// ---------------------------------------------------------------------------
__global__ void __launch_bounds__(NTHREADS, 2)
attn_kernel(const float* __restrict__ qkv, float* __restrict__ out) {
    extern __shared__ float smem[];
    float* sbias = smem;  // 4096 floats, shared by all warps (same h)

    const int tid  = threadIdx.x;
    const int lane = tid & 31;
    const int w    = tid >> 5;
    const int h    = blockIdx.x;
    const int b    = blockIdx.y * WARPS_PER_CTA + w;
    const bool active = (b < 2048);

    float* sk = smem + 4096 + w * 4096;  // 64 x 32
    float* sv = sk + 2048;               // 64 x 32

    // ---- stage bias tile (all threads participate) ----------------------
    {
        const float4* gb = (const float4*)(g_biasT + h * 4096);
#pragma unroll
        for (int i = tid; i < 1024; i += NTHREADS)
            ((float4*)sbias)[i] = gb[i];
    }

    // ---- stage k, v into per-warp smem + q rows into registers ----------
    ulonglong2 q0[8], q1[8];
    if (active) {
        const float* base = qkv + (size_t)b * (NWIN * 576) + h * HD;
        const int r4 = lane >> 3;  // 0..3
        const int f  = lane & 7;   // 0..7
#pragma unroll
        for (int i = 0; i < 16; i++) {
            const int n = i * 4 + r4;
            const float* g = base + n * 576 + f * 4;
            float4 kx = *(const float4*)(g + 192);
            float4 vx = *(const float4*)(g + 384);
            *(float4*)(sk + n * 32 + f * 4) = kx;
            *(float4*)(sv + n * 32 + f * 4) = vx;
        }
        const float* qr0 = base + lane * 576;
        const float* qr1 = base + (lane + 32) * 576;
#pragma unroll
        for (int i = 0; i < 8; i++) {
            q0[i] = *(const ulonglong2*)(qr0 + i * 4);
            q1[i] = *(const ulonglong2*)(qr1 + i * 4);
        }
    }
    __syncthreads();
    if (!active) return;

    // ---- software-pipelined streaming attention over m -------------------
    u64 o0[16], o1[16];
#pragma unroll
    for (int j = 0; j < 16; j++) { o0[j] = 0ull; o1[j] = 0ull; }
    u64 sums = 0ull;  // (sum row0, sum row1)

    const float* bias_l = sbias + 2 * lane;

    float e0p = 0.0f, e1p = 0.0f;   // e from previous iteration
    ulonglong2 vprev[8];            // v row from previous iteration (finite)
#pragma unroll
    for (int j = 0; j < 8; j++) vprev[j] = ((const ulonglong2*)sv)[j];

#pragma unroll 2
    for (int m = 0; m < NWIN; m++) {
        // (1) issue k[m] loads — consumed by the dot below
        ulonglong2 kc[8];
        const ulonglong2* krow = (const ulonglong2*)(sk + m * 32);
#pragma unroll
        for (int j = 0; j < 8; j++) kc[j] = krow[j];

        // (2) PV for previous iteration — pure reg math hides k latency
        {
            const u64 ea = pack2(e0p, e0p);
            const u64 eb = pack2(e1p, e1p);
#pragma unroll
            for (int j = 0; j < 8; j++) {
                o0[2 * j]     = fma2(ea, vprev[j].x, o0[2 * j]);
                o0[2 * j + 1] = fma2(ea, vprev[j].y, o0[2 * j + 1]);
                o1[2 * j]     = fma2(eb, vprev[j].x, o1[2 * j]);
                o1[2 * j + 1] = fma2(eb, vprev[j].y, o1[2 * j + 1]);
            }
        }

        // (3) dot products on k[m] (packed over d)
        u64 d0a = 0ull, d0b = 0ull, d1a = 0ull, d1b = 0ull;
#pragma unroll
        for (int j = 0; j < 8; j += 2) {
            ulonglong2 ka = kc[j];
            ulonglong2 kb = kc[j + 1];
            d0a = fma2(q0[j].x, ka.x, d0a);
            d0b = fma2(q0[j].y, ka.y, d0b);
            d1a = fma2(q1[j].x, ka.x, d1a);
            d1b = fma2(q1[j].y, ka.y, d1b);
            d0a = fma2(q0[j + 1].x, kb.x, d0a);
            d0b = fma2(q0[j + 1].y, kb.y, d0b);
            d1a = fma2(q1[j + 1].x, kb.x, d1a);
            d1b = fma2(q1[j + 1].y, kb.y, d1b);
        }

        // (4) issue v[m] loads — consumed next iteration
        const ulonglong2* vrow = (const ulonglong2*)(sv + m * 32);
#pragma unroll
        for (int j = 0; j < 8; j++) vprev[j] = vrow[j];

        // (5) exp chain — result consumed next iteration
        float2 bf = unpack2(*(const u64*)(bias_l + m * 64));  // log2e-scaled
        float2 p0 = unpack2(add2(d0a, d0b));
        float2 p1 = unpack2(add2(d1a, d1b));
        e0p = ex2f(fmaf(p0.x + p0.y, ATT_SCALE * LOG2E, bf.x));
        e1p = ex2f(fmaf(p1.x + p1.y, ATT_SCALE * LOG2E, bf.y));
        sums = add2(sums, pack2(e0p, e1p));
    }

    // drain: final PV for m = 63
    {
        const u64 ea = pack2(e0p, e0p);
        const u64 eb = pack2(e1p, e1p);
#pragma unroll
        for (int j = 0; j < 8; j++) {
            o0[2 * j]     = fma2(ea, vprev[j].x, o0[2 * j]);
            o0[2 * j + 1] = fma2(ea, vprev[j].y, o0[2 * j + 1]);
            o1[2 * j]     = fma2(eb, vprev[j].x, o1[2 * j]);
            o1[2 * j + 1] = fma2(eb, vprev[j].y, o1[2 * j + 1]);
        }
    }

    // ---- epilogue: normalize + store ------------------------------------
    float2 s = unpack2(sums);
    const float inv0 = 1.0f / s.x;
    const float inv1 = 1.0f / s.y;

    float* orow0 = out + (size_t)b * (NWIN * 192) + lane * 192 + h * HD;
    float* orow1 = orow0 + 32 * 192;
#pragma unroll
    for (int j = 0; j < 8; j++) {
        float2 a0 = unpack2(o0[2 * j]);
        float2 a1 = unpack2(o0[2 * j + 1]);
        *(float4*)(orow0 + 4 * j) =
            make_float4(a0.x * inv0, a0.y * inv0, a1.x * inv0, a1.y * inv0);
        float2 c0 = unpack2(o1[2 * j]);
        float2 c1 = unpack2(o1[2 * j + 1]);
        *(float4*)(orow1 + 4 * j) =
            make_float4(c0.x * inv1, c0.y * inv1, c1.x * inv1, c1.y * inv1);
    }
}

// ---------------------------------------------------------------------------
extern "C" void kernel_launch(void* const* d_in, const int* in_sizes, int n_in,
                              void* d_out, int out_size) {
    const float* qkv = (const float*)d_in[0];
    const float* rel = (const float*)d_in[1];
    const float* w1  = (const float*)d_in[2];
    const float* b1  = (const float*)d_in[3];
    const float* w2  = (const float*)d_in[4];
    const float* b2  = (const float*)d_in[5];
    float* out = (float*)d_out;

    const int smem_bytes = (4096 + WARPS_PER_CTA * 4096) * sizeof(float);  // 96 KB
    cudaFuncSetAttribute(attn_kernel, cudaFuncAttributeMaxDynamicSharedMemorySize,
                         smem_bytes);

    bias_kernel<<<16, 256>>>(rel, w1, b1, w2, b2);
    const int gy = (2048 + WARPS_PER_CTA - 1) / WARPS_PER_CTA;  // 410
    attn_kernel<<<dim3(NH, gy), NTHREADS, smem_bytes>>>(qkv, out);
}

// round 8
// speedup vs baseline: 1.0654x; 1.0232x over previous
#include <cuda_runtime.h>

#define NWIN 64
#define HD   32
#define NH   6
#define ATT_SCALE 0.17677669529663687f   // 32^-0.5
#define LOG2E 1.4426950408889634f
#define NTHREADS 256                      // 8 warps, 4 windows per CTA
#define WIN_PER_CTA 4

typedef unsigned long long u64;

__device__ float g_biasT[NH * NWIN * NWIN];  // [h][m][r], pre-scaled by log2e

static __device__ __forceinline__ u64 fma2(u64 a, u64 b, u64 c) {
    u64 d;
    asm("fma.rn.f32x2 %0, %1, %2, %3;" : "=l"(d) : "l"(a), "l"(b), "l"(c));
    return d;
}
static __device__ __forceinline__ u64 add2(u64 a, u64 b) {
    u64 d;
    asm("add.rn.f32x2 %0, %1, %2;" : "=l"(d) : "l"(a), "l"(b));
    return d;
}
static __device__ __forceinline__ u64 pack2(float x, float y) {
    u64 d;
    asm("mov.b64 %0, {%1, %2};" : "=l"(d) : "f"(x), "f"(y));
    return d;
}
static __device__ __forceinline__ float2 unpack2(u64 u) {
    float2 r;
    asm("mov.b64 {%0, %1}, %2;" : "=f"(r.x), "=f"(r.y) : "l"(u));
    return r;
}
static __device__ __forceinline__ float ex2f(float x) {
    float y;
    asm("ex2.approx.ftz.f32 %0, %1;" : "=f"(y) : "f"(x));
    return y;
}

// ---------------------------------------------------------------------------
// Kernel 1: relative-position bias MLP  [64,64,2] -> g_biasT[h][m][r]*log2e
// ---------------------------------------------------------------------------
__global__ void __launch_bounds__(256)
bias_kernel(const float* __restrict__ rel, const float* __restrict__ w1,
            const float* __restrict__ b1, const float* __restrict__ w2,
            const float* __restrict__ b2) {
    __shared__ float s_w1a[256];
    __shared__ float s_w1b[256];
    __shared__ float s_b1[256];
    __shared__ float s_w2[256 * NH];

    const int tid = threadIdx.x;
    s_w1a[tid] = w1[tid];
    s_w1b[tid] = w1[256 + tid];
    s_b1[tid]  = b1[tid];
#pragma unroll
    for (int i = tid; i < 256 * NH; i += 256) s_w2[i] = w2[i];
    __syncthreads();

    const int idx = blockIdx.x * 256 + tid;  // r*64 + m
    const float r0 = rel[idx * 2 + 0];
    const float r1 = rel[idx * 2 + 1];

    float acc[NH];
#pragma unroll
    for (int o = 0; o < NH; o++) acc[o] = 0.0f;

#pragma unroll 4
    for (int hh = 0; hh < 256; hh++) {
        float a = fmaf(r0, s_w1a[hh], fmaf(r1, s_w1b[hh], s_b1[hh]));
        a = fmaxf(a, 0.0f);
#pragma unroll
        for (int o = 0; o < NH; o++) acc[o] = fmaf(a, s_w2[hh * NH + o], acc[o]);
    }
    const int r = idx >> 6;
    const int m = idx & 63;
#pragma unroll
    for (int o = 0; o < NH; o++)
        g_biasT[o * 4096 + m * 64 + r] = (acc[o] + b2[o]) * LOG2E;
}

// ---------------------------------------------------------------------------
// Kernel 2: a WARP PAIR owns one (b,h) window; k/v tile shared in smem.
//   Each lane owns ONE query row: row = (warp&1)*32 + lane.
//   k[m]/v[m] via uniform-address broadcast LDS; streaming softmax.
// ---------------------------------------------------------------------------
__global__ void __launch_bounds__(NTHREADS, 2)
attn_kernel(const float* __restrict__ qkv, float* __restrict__ out) {
    extern __shared__ float smem[];
    float* sbias = smem;  // 4096 floats [m][r], shared by all warps (same h)

    const int tid  = threadIdx.x;
    const int lane = tid & 31;
    const int w    = tid >> 5;
    const int pair = w >> 1;      // 0..3  (window slot)
    const int par  = w & 1;       // row half
    const int h    = blockIdx.x;
    const int b    = blockIdx.y * WIN_PER_CTA + pair;
    const int row  = par * 32 + lane;

    float* sk = smem + 4096 + pair * 4096;  // 64 x 32
    float* sv = sk + 2048;                  // 64 x 32

    // ---- stage bias tile (all threads) -----------------------------------
    {
        const float4* gb = (const float4*)(g_biasT + h * 4096);
#pragma unroll
        for (int i = tid; i < 1024; i += NTHREADS)
            ((float4*)sbias)[i] = gb[i];
    }

    // ---- stage k, v (warp stages its 32 rows) + q row into registers -----
    const float* base = qkv + (size_t)b * (NWIN * 576) + h * HD;
    {
        const int r4 = lane >> 3;  // 0..3
        const int f  = lane & 7;   // 0..7
#pragma unroll
        for (int i = 0; i < 8; i++) {
            const int n = par * 32 + i * 4 + r4;
            const float* g = base + n * 576 + f * 4;
            float4 kx = *(const float4*)(g + 192);
            float4 vx = *(const float4*)(g + 384);
            *(float4*)(sk + n * 32 + f * 4) = kx;
            *(float4*)(sv + n * 32 + f * 4) = vx;
        }
    }
    ulonglong2 q[8];
    {
        const float* qr = base + row * 576;
#pragma unroll
        for (int i = 0; i < 8; i++) q[i] = *(const ulonglong2*)(qr + i * 4);
    }
    __syncthreads();

    // ---- streaming attention over key index m -----------------------------
    u64 o[16];
#pragma unroll
    for (int j = 0; j < 16; j++) o[j] = 0ull;
    float sum = 0.0f;

    const float* bias_r = sbias + row;

#pragma unroll 2
    for (int m = 0; m < NWIN; m++) {
        const ulonglong2* krow = (const ulonglong2*)(sk + m * 32);
        const ulonglong2* vrow = (const ulonglong2*)(sv + m * 32);

        // dot product (packed over d): 2 chains of depth 8
        u64 da = 0ull, db = 0ull;
#pragma unroll
        for (int j = 0; j < 8; j += 2) {
            ulonglong2 ka = krow[j];
            ulonglong2 kb = krow[j + 1];
            da = fma2(q[j].x, ka.x, da);
            db = fma2(q[j].y, ka.y, db);
            da = fma2(q[j + 1].x, kb.x, da);
            db = fma2(q[j + 1].y, kb.y, db);
        }
        const float bf = bias_r[m * 64];                // log2e-scaled bias
        float2 p = unpack2(add2(da, db));
        const float e = ex2f(fmaf(p.x + p.y, ATT_SCALE * LOG2E, bf));
        sum += e;
        const u64 ep = pack2(e, e);

#pragma unroll
        for (int j = 0; j < 8; j++) {
            ulonglong2 vx = vrow[j];
            o[2 * j]     = fma2(ep, vx.x, o[2 * j]);
            o[2 * j + 1] = fma2(ep, vx.y, o[2 * j + 1]);
        }
    }

    // ---- epilogue: normalize + store --------------------------------------
    const float inv = 1.0f / sum;
    float* orow = out + (size_t)b * (NWIN * 192) + row * 192 + h * HD;
#pragma unroll
    for (int j = 0; j < 8; j++) {
        float2 a0 = unpack2(o[2 * j]);
        float2 a1 = unpack2(o[2 * j + 1]);
        *(float4*)(orow + 4 * j) =
            make_float4(a0.x * inv, a0.y * inv, a1.x * inv, a1.y * inv);
    }
}

// ---------------------------------------------------------------------------
extern "C" void kernel_launch(void* const* d_in, const int* in_sizes, int n_in,
                              void* d_out, int out_size) {
    const float* qkv = (const float*)d_in[0];
    const float* rel = (const float*)d_in[1];
    const float* w1  = (const float*)d_in[2];
    const float* b1  = (const float*)d_in[3];
    const float* w2  = (const float*)d_in[4];
    const float* b2  = (const float*)d_in[5];
    float* out = (float*)d_out;

    const int smem_bytes = (4096 + WIN_PER_CTA * 4096) * sizeof(float);  // 80 KB
    cudaFuncSetAttribute(attn_kernel, cudaFuncAttributeMaxDynamicSharedMemorySize,
                         smem_bytes);

    bias_kernel<<<16, 256>>>(rel, w1, b1, w2, b2);
    attn_kernel<<<dim3(NH, 2048 / WIN_PER_CTA), NTHREADS, smem_bytes>>>(qkv, out);
}